// round 13
// baseline (speedup 1.0000x reference)
#include <cuda_runtime.h>
#include <math.h>

// ---------------------------------------------------------------------------
// DE3 fused: 256-bin histogram entropy, single kernel, TMA-staged,
// DECOUPLED producer/consumer (no __syncthreads in the main loop).
//   out = B * (8 + sum_i p_i log2 p_i),  p_i = counts[i] / (2048*2048)
//
// R12 (68us) lost ~1500 cyc/chunk to lock-step: full __syncthreads before
// every refill. This round: per-buffer EMPTY mbarriers (arrive count = 128).
// Consumers arrive after using a buffer and immediately proceed to the next;
// t0 waits the empty barrier's previous-round parity before reissuing TMA.
// Warps skew freely within the 3-deep ring.
//
// Layout per block (128 thr):
//   [0,64K)    per-thread u16 histograms (R7 proven):
//                counter(thread,bin) @ warp*16384 + bin*64 + lane*2
//   [64K,112K) stage ring: 3 x 16 KB (1024 float4)
//   [112K,..)  full[3], empty[3] mbarriers
// 296 blocks (2/SM). 16384 chunks; <=56/block -> <=1792 elems/thread
// (u16 safe; packed reduction carry-free).
// ---------------------------------------------------------------------------

#define NUM_BINS 256
#define THREADS  128
#define BLOCKS   296
#define HISTO_BYTES 65536
#define NBUF      3
#define CHUNK_F4  1024
#define CHUNK_BYTES 16384
#define STAGE_OFF  HISTO_BYTES
#define MBAR_OFF  (HISTO_BYTES + NBUF * CHUNK_BYTES)     // 114688
#define SMEM_BYTES (MBAR_OFF + 64)                       // 114752

__device__ unsigned int g_counts[NUM_BINS];   // zero-init at load
__device__ unsigned int g_done;

__device__ __forceinline__ void mbar_init(unsigned addr, unsigned cnt) {
    asm volatile("mbarrier.init.shared.b64 [%0], %1;" :: "r"(addr), "r"(cnt) : "memory");
}
__device__ __forceinline__ void mbar_expect_tx(unsigned addr, unsigned bytes) {
    asm volatile("mbarrier.arrive.expect_tx.shared.b64 _, [%0], %1;"
                 :: "r"(addr), "r"(bytes) : "memory");
}
__device__ __forceinline__ void mbar_arrive(unsigned addr) {
    asm volatile("mbarrier.arrive.shared.b64 _, [%0];" :: "r"(addr) : "memory");
}
__device__ __forceinline__ void mbar_wait(unsigned addr, unsigned parity) {
    unsigned done;
    asm volatile(
        "{\n\t.reg .pred p;\n\t"
        "mbarrier.try_wait.parity.acquire.cta.shared::cta.b64 p, [%1], %2;\n\t"
        "selp.b32 %0, 1, 0, p;\n\t}"
        : "=r"(done) : "r"(addr), "r"(parity) : "memory");
    if (!done) {
        asm volatile(
            "{\n\t.reg .pred P1;\n\t"
            "W_%=:\n\t"
            "mbarrier.try_wait.parity.acquire.cta.shared::cta.b64 P1, [%0], %1, 0x989680;\n\t"
            "@P1 bra.uni D_%=;\n\t"
            "bra.uni W_%=;\n\t"
            "D_%=:\n\t}"
            :: "r"(addr), "r"(parity) : "memory");
    }
}
__device__ __forceinline__ void tma_1d(unsigned dst, const void* src,
                                       unsigned bytes, unsigned mbar) {
    asm volatile(
        "cp.async.bulk.shared::cluster.global.mbarrier::complete_tx::bytes "
        "[%0], [%1], %2, [%3];"
        :: "r"(dst), "l"(src), "r"(bytes), "r"(mbar) : "memory");
}
__device__ __forceinline__ void fence_proxy() {
    asm volatile("fence.proxy.async.shared::cta;" ::: "memory");
}

__global__ void __launch_bounds__(THREADS)
de3_fused(const float4* __restrict__ in4, int n4,
          const float* __restrict__ in, int n,
          float* __restrict__ out)
{
    extern __shared__ unsigned char smem[];
    unsigned smem_u32;
    asm("{ .reg .u64 t; cvta.to.shared.u64 t, %1; cvt.u32.u64 %0, t; }"
        : "=r"(smem_u32) : "l"(smem));
    const unsigned stage_u32 = smem_u32 + STAGE_OFF;
    const unsigned fullb     = smem_u32 + MBAR_OFF;        // full[s]  at +8s
    const unsigned emptyb    = smem_u32 + MBAR_OFF + 32;   // empty[s] at +8s

    const unsigned t    = threadIdx.x;
    const unsigned lane = t & 31u;
    const unsigned warp = t >> 5;
    const unsigned lanebase = (warp << 14) + (lane << 1);  // warp*16KB + lane*2

    // zero private histograms
    {
        uint4* z = reinterpret_cast<uint4*>(smem);
        #pragma unroll
        for (int i = t; i < HISTO_BYTES / 16; i += THREADS)
            z[i] = make_uint4(0u, 0u, 0u, 0u);
    }
    if (t == 0) {
        #pragma unroll
        for (int s = 0; s < NBUF; ++s) {
            mbar_init(fullb  + 8u * s, 1u);
            mbar_init(emptyb + 8u * s, THREADS);
        }
        fence_proxy();
    }
    __syncthreads();       // barriers + zeroed histo visible to all

    const int G       = gridDim.x;
    const int nchunks = n4 >> 10;                 // 1024 float4 per chunk

    // ---- prologue: t0 launches the first NBUF chunk copies ----------------
    if (t == 0) {
        #pragma unroll
        for (int s = 0; s < NBUF; ++s) {
            int c = blockIdx.x + s * G;
            if (c < nchunks) {
                mbar_expect_tx(fullb + 8u * s, CHUNK_BYTES);
                tma_1d(stage_u32 + (unsigned)s * CHUNK_BYTES,
                       in4 + (size_t)c * CHUNK_F4, CHUNK_BYTES, fullb + 8u * s);
            }
        }
    }

    // R7's proven u16 bump (1 IMAD address)
    #define DE3_BUMP(V) do {                                                  \
        unsigned b_ = __float2uint_rz(fminf((V), 255.0f));                    \
        unsigned short* c_ =                                                  \
            reinterpret_cast<unsigned short*>(smem + (b_ * 64u + lanebase));  \
        *c_ = (unsigned short)(*c_ + 1u);                                     \
    } while (0)
    #define DE3_BUMP4(Q) do { DE3_BUMP((Q).x); DE3_BUMP((Q).y);              \
                              DE3_BUMP((Q).z); DE3_BUMP((Q).w); } while (0)

    // ---- main loop: decoupled consume + arrive; t0 refills 3 behind -------
    const float4* stage_f4 = reinterpret_cast<const float4*>(smem + STAGE_OFF);
    int c = blockIdx.x;
    int buf = 0;                 // c's ring slot
    unsigned round = 0u;         // c's use-round of that slot
    while (c < nchunks) {
        mbar_wait(fullb + 8u * buf, round & 1u);

        const float4* slot = stage_f4 + buf * CHUNK_F4 + t;
        #pragma unroll
        for (int k = 0; k < CHUNK_F4 / THREADS; ++k) {        // 8 LDS.128
            float4 v = slot[k * THREADS];
            DE3_BUMP4(v);
        }
        mbar_arrive(emptyb + 8u * buf);      // done with (buf, round)

        if (t == 0) {
            int cn = c + NBUF * G;
            if (cn < nchunks) {
                // wait until ALL threads have consumed (buf, round)
                mbar_wait(emptyb + 8u * buf, round & 1u);
                fence_proxy();
                mbar_expect_tx(fullb + 8u * buf, CHUNK_BYTES);
                tma_1d(stage_u32 + (unsigned)buf * CHUNK_BYTES,
                       in4 + (size_t)cn * CHUNK_F4, CHUNK_BYTES, fullb + 8u * buf);
            }
        }
        c += G;
        if (++buf == NBUF) { buf = 0; ++round; }
    }

    // ---- tails: float4 remainder, then scalar remainder -------------------
    for (int i = nchunks * CHUNK_F4 + blockIdx.x * THREADS + (int)t;
         i < n4; i += G * THREADS) {
        float4 v = __ldcs(in4 + i);
        DE3_BUMP4(v);
    }
    if (blockIdx.x == 0 && (int)t < (n & 3)) {
        float v = in[(n & ~3) + (int)t];
        DE3_BUMP(v);
    }
    #undef DE3_BUMP4
    #undef DE3_BUMP
    __syncthreads();

    // ---- block reduction (R7, proven): thread j sums bins j, j+128 --------
    const unsigned j = t;
    unsigned tot0 = 0u, tot1 = 0u;
    #pragma unroll
    for (int w = 0; w < 4; ++w) {
        const unsigned base0 = ((unsigned)w << 14) + j * 64u;
        const unsigned base1 = ((unsigned)w << 14) + (j + 128u) * 64u;
        unsigned acc0 = 0u, acc1 = 0u;
        #pragma unroll
        for (unsigned s = 0; s < 16; ++s) {
            unsigned k = (((j >> 1) + s) & 15u) << 2;
            acc0 += *reinterpret_cast<const unsigned*>(smem + base0 + k);
            acc1 += *reinterpret_cast<const unsigned*>(smem + base1 + k);
        }
        tot0 += (acc0 & 0xFFFFu) + (acc0 >> 16);
        tot1 += (acc1 & 0xFFFFu) + (acc1 >> 16);
    }
    atomicAdd(&g_counts[j],       tot0);
    atomicAdd(&g_counts[j + 128], tot1);

    // ---- last-block finalize ----------------------------------------------
    __threadfence();
    __shared__ unsigned ticket;
    if (t == 0) ticket = atomicAdd(&g_done, 1u);
    __syncthreads();

    if (ticket == gridDim.x - 1) {
        const float inv_temp = 1.0f / 4194304.0f;   // 1/(2048*2048)
        unsigned c0 = __ldcg(&g_counts[j]);
        unsigned c1 = __ldcg(&g_counts[j + 128]);
        double term = 0.0;
        if (c0) { float p = (float)c0 * inv_temp; term += (double)(p * log2f(p)); }
        if (c1) { float p = (float)c1 * inv_temp; term += (double)(p * log2f(p)); }

        #pragma unroll
        for (int o = 16; o > 0; o >>= 1)
            term += __shfl_down_sync(0xffffffffu, term, o);

        __shared__ double sred[4];
        if ((j & 31u) == 0u) sred[j >> 5] = term;
        __syncthreads();
        if (j == 0) {
            double s = sred[0] + sred[1] + sred[2] + sred[3];
            float B = (float)(n >> 22);              // n / (2048*2048)
            out[0] = (float)((double)B * (8.0 + s));
        }
        __syncthreads();
        // reset globals for the next graph replay
        g_counts[j] = 0u;
        g_counts[j + 128] = 0u;
        if (j == 0) g_done = 0u;
    }
}

extern "C" void kernel_launch(void* const* d_in, const int* in_sizes, int n_in,
                              void* d_out, int out_size) {
    const float* img = (const float*)d_in[0];
    int n = in_sizes[0];
    cudaFuncSetAttribute(de3_fused,
                         cudaFuncAttributeMaxDynamicSharedMemorySize, SMEM_BYTES);
    de3_fused<<<BLOCKS, THREADS, SMEM_BYTES>>>(
        (const float4*)img, n >> 2, img, n, (float*)d_out);
}